// round 8
// baseline (speedup 1.0000x reference)
#include <cuda_runtime.h>
#include <cuda_bf16.h>
#include <mma.h>
#include <cstdint>

using namespace nvcuda;

// ---------------- problem constants ----------------
#define B_   64
#define T_   128
#define F_   16
#define H_   512
#define G_   2048          // 4*H
#define R_   128           // S*B rows in recurrence
#define NROW 8192          // B*T
#define KE   1024          // t_emb width

// ---------------- static device scratch (no allocation) ----------------
__device__ float d_Emb[(size_t)NROW * KE];          // 32 MB tf32-rounded t_emb
__device__ float d_gx[(size_t)T_ * R_ * G_];        // 128 MB per-step gate inputs
__device__ float d_Wc0[G_ * 8];
__device__ float d_Wc1[G_ * 6];
__device__ float d_b0[G_];
__device__ float d_b1[G_];
__device__ float d_Hbuf[2 * R_ * H_];               // double-buffered h (tf32-rounded)
__device__ float d_hfin[B_ * 2 * H_];               // exact h at lengths-1
__device__ unsigned d_cnt;

__device__ __forceinline__ float tf32r(float x) {
    unsigned u;
    asm("cvt.rna.tf32.f32 %0, %1;" : "=r"(u) : "f"(x));
    return __uint_as_float(u);
}

__device__ __forceinline__ float wred(float v) {
#pragma unroll
    for (int o = 16; o; o >>= 1) v += __shfl_down_sync(0xffffffffu, v, o);
    return v;
}

// ================= K0: fold input linears through W_ih[:, :512] ============
// Wc0[g][j] = sum_k W_ih[g,k] * W_is0[k,j]   (j<8); Wc1 similarly (j<6)
// b0[g] = b_ih[g]+b_hh[g]+sum_k W_ih[g,k]*b_is0[k]; b1 with b_is1.
// Also resets the grid-barrier counter (stream-ordered before k_rnn).
__global__ void k_setup(const float* __restrict__ Wih,
                        const float* __restrict__ Wis0, const float* __restrict__ bis0,
                        const float* __restrict__ Wis1, const float* __restrict__ bis1,
                        const float* __restrict__ bih,  const float* __restrict__ bhh) {
    if (blockIdx.x == 0 && threadIdx.x == 0) d_cnt = 0u;
    int gw = (blockIdx.x * blockDim.x + threadIdx.x) >> 5;   // warp id == gate row
    int lane = threadIdx.x & 31;
    if (gw >= G_) return;
    float a0[8], a1[6], s0 = 0.f, s1 = 0.f;
#pragma unroll
    for (int j = 0; j < 8; j++) a0[j] = 0.f;
#pragma unroll
    for (int j = 0; j < 6; j++) a1[j] = 0.f;
    const float* wr = Wih + (size_t)gw * 1536;
    for (int k = lane; k < 512; k += 32) {
        float w = wr[k];
#pragma unroll
        for (int j = 0; j < 8; j++) a0[j] += w * Wis0[k * 8 + j];
#pragma unroll
        for (int j = 0; j < 6; j++) a1[j] += w * Wis1[k * 6 + j];
        s0 += w * bis0[k];
        s1 += w * bis1[k];
    }
#pragma unroll
    for (int j = 0; j < 8; j++) a0[j] = wred(a0[j]);
#pragma unroll
    for (int j = 0; j < 6; j++) a1[j] = wred(a1[j]);
    s0 = wred(s0); s1 = wred(s1);
    if (lane == 0) {
#pragma unroll
        for (int j = 0; j < 8; j++) d_Wc0[gw * 8 + j] = a0[j];
#pragma unroll
        for (int j = 0; j < 6; j++) d_Wc1[gw * 6 + j] = a1[j];
        float bb = bih[gw] + bhh[gw];
        d_b0[gw] = bb + s0;
        d_b1[gw] = bb + s1;
    }
}

// ================= K1: timestep embeddings (tf32-rounded) ==================
// Emb[n][k]: k<256 cos(x0*f), 256-511 sin(x0*f), 512-767 cos(x1*f), 768-1023 sin(x1*f)
__global__ void k_emb(const float* __restrict__ x) {
    int n = blockIdx.x;
    float x0 = x[n * 16 + 0];
    float x1 = x[n * 16 + 1];
    float* row = d_Emb + (size_t)n * KE;
#pragma unroll
    for (int i = 0; i < 8; i++) {
        int k = threadIdx.x + 128 * i;
        int j = k & 255;
        int reg = k >> 8;
        float f = expf(-9.210340371976184f * (float)j * (1.0f / 256.0f));
        float arg = (reg < 2 ? x0 : x1) * f;
        float v = (reg & 1) ? sinf(arg) : cosf(arg);
        row[k] = tf32r(v);
    }
}

// ================= K2: init H(0) for both segments =========================
__global__ void k_init(const float* __restrict__ h0) {
    int r = blockIdx.x;           // 0..127, r = s*64 + b
    int b = r & 63;
    for (int d = threadIdx.x; d < H_; d += blockDim.x)
        d_Hbuf[r * H_ + d] = tf32r(h0[b * H_ + d]);
}

// ================= K3: big GEMM  gx = Emb @ W_t^T (+ e-part, dual parity) ==
// CTA tile 128(m=n-rows) x 128(g-cols), K=1024 in chunks of 16. tf32 wmma.
__global__ __launch_bounds__(256) void k_gemm1(const float* __restrict__ x,
                                               const float* __restrict__ Wih) {
    __shared__ float As[128 * 20];
    __shared__ float Bs[128 * 20];
    __shared__ float Pt[8 * 320];        // per-warp 16x20 epilogue patch
    __shared__ float Xs[128 * 14];       // x cols 2..15 for the 128 rows
    __shared__ float Wc[128 * 16];       // per col: [8 wc0][6 wc1][b0][b1]

    const int g0 = blockIdx.x * 128;
    const int m0 = blockIdx.y * 128;
    const int tid = threadIdx.x;
    const int wid = tid >> 5, lane = tid & 31;
    const int wm = wid >> 2, wn = wid & 3;   // warps 2(M) x 4(N); warp tile 64x32

    for (int v = tid; v < 128 * 14; v += 256) {
        int i = v / 14, j = v - i * 14;
        Xs[v] = x[(m0 + i) * 16 + 2 + j];
    }
    for (int v = tid; v < 2048; v += 256) {
        int c = v >> 4, j = v & 15;
        int gg = g0 + c;
        float val;
        if (j < 8)       val = d_Wc0[gg * 8 + j];
        else if (j < 14) val = d_Wc1[gg * 6 + (j - 8)];
        else if (j == 14) val = d_b0[gg];
        else              val = d_b1[gg];
        Wc[v] = val;
    }

    wmma::fragment<wmma::accumulator, 16, 16, 8, float> acc[4][2];
#pragma unroll
    for (int i = 0; i < 4; i++)
#pragma unroll
        for (int j = 0; j < 2; j++) wmma::fill_fragment(acc[i][j], 0.0f);

    for (int kc = 0; kc < 64; kc++) {
        __syncthreads();
        // stage A: 128 rows x 16 (Emb pre-rounded)
        for (int v = tid; v < 512; v += 256) {
            int i = v >> 2, c4 = v & 3;
            float4 t4 = *(const float4*)(d_Emb + (size_t)(m0 + i) * KE + kc * 16 + c4 * 4);
            *(float4*)&As[i * 20 + c4 * 4] = t4;
        }
        // stage B: 128 g-rows x 16 (raw W_ih; rounded at fragment load)
        for (int v = tid; v < 512; v += 256) {
            int gi = v >> 2, c4 = v & 3;
            float4 t4 = *(const float4*)(Wih + (size_t)(g0 + gi) * 1536 + 512 + kc * 16 + c4 * 4);
            *(float4*)&Bs[gi * 20 + c4 * 4] = t4;
        }
        __syncthreads();
#pragma unroll
        for (int ks = 0; ks < 2; ks++) {
            wmma::fragment<wmma::matrix_b, 16, 16, 8, wmma::precision::tf32, wmma::col_major> bf[2];
#pragma unroll
            for (int nn = 0; nn < 2; nn++) {
                wmma::load_matrix_sync(bf[nn], &Bs[(wn * 32 + nn * 16) * 20 + ks * 8], 20);
#pragma unroll
                for (int e = 0; e < bf[nn].num_elements; e++)
                    bf[nn].x[e] = wmma::__float_to_tf32(bf[nn].x[e]);
            }
#pragma unroll
            for (int tm = 0; tm < 4; tm++) {
                wmma::fragment<wmma::matrix_a, 16, 16, 8, wmma::precision::tf32, wmma::row_major> af;
                wmma::load_matrix_sync(af, &As[(wm * 64 + tm * 16) * 20 + ks * 8], 20);
#pragma unroll
                for (int nn = 0; nn < 2; nn++)
                    wmma::mma_sync(acc[tm][nn], af, bf[nn], acc[tm][nn]);
            }
        }
    }

    // epilogue: write both parities with folded e-parts + biases
#pragma unroll
    for (int nn = 0; nn < 2; nn++) {
        int cl = wn * 32 + nn * 16 + (lane & 15);
        float wcj[14];
#pragma unroll
        for (int j = 0; j < 14; j++) wcj[j] = Wc[cl * 16 + j];
        float bb0 = Wc[cl * 16 + 14], bb1 = Wc[cl * 16 + 15];
        int g = g0 + cl;
#pragma unroll
        for (int tm = 0; tm < 4; tm++) {
            wmma::store_matrix_sync(&Pt[wid * 320], acc[tm][nn], 20, wmma::mem_row_major);
            __syncwarp();
#pragma unroll
            for (int i2 = 0; i2 < 8; i2++) {
                int pr = (lane >> 4) + 2 * i2;
                int ml = wm * 64 + tm * 16 + pr;
                float dd = Pt[wid * 320 + pr * 20 + (lane & 15)];
                float e0 = 0.f, e1 = 0.f;
#pragma unroll
                for (int j = 0; j < 8; j++) e0 += Xs[ml * 14 + j] * wcj[j];
#pragma unroll
                for (int j = 0; j < 6; j++) e1 += Xs[ml * 14 + 8 + j] * wcj[8 + j];
                int n = m0 + ml;
                int b = n >> 7, rem = n & 127;
                int s = rem >> 6, u = rem & 63;
                int r = s * 64 + b;
                size_t base = ((size_t)(2 * u) * R_ + r) * G_ + g;
                d_gx[base] = dd + e0 + bb0;
                d_gx[base + (size_t)R_ * G_] = dd + e1 + bb1;
            }
            __syncwarp();
        }
    }
}

// ================= K4: persistent LSTM recurrence ==========================
// 128 CTAs: rb = cid>>5 (32 rows), dg = cid&31 (16 hidden dims -> 4x16 gate cols)
#define RNN_SMEM_BYTES ((64 * 520 + 32 * 72 + 32 * 68 + 32 * 16) * 4 + 32 * 4)
__global__ __launch_bounds__(256) void k_rnn(const float* __restrict__ Whh,
                                             const float* __restrict__ c0,
                                             const int* __restrict__ lengths) {
    extern __shared__ float sm[];
    float* Ws = sm;                      // 64 x 520  (rows: q*16+j -> gate q*512+d0+j)
    float* Hs = Ws + 64 * 520;           // 32 x 72
    float* Gs = Hs + 32 * 72;            // 32 x 68
    float* Cs = Gs + 32 * 68;            // 32 x 16
    int*   Ls = (int*)(Cs + 32 * 16);    // 32

    const int cid = blockIdx.x;
    const int rb = cid >> 5, dg = cid & 31;
    const int r0 = rb * 32, d0 = dg * 16;
    const int tid = threadIdx.x;
    const int wid = tid >> 5;
    const int wm = wid >> 2, wn = wid & 3;   // warps 2(M rows) x 4(gate type q)

    // load W_hh slice (tf32-rounded), c-state, lengths
    for (int idx = tid; idx < 64 * 512; idx += 256) {
        int row = idx >> 9, k = idx & 511;
        int q = row >> 4, j = row & 15;
        Ws[row * 520 + k] = tf32r(Whh[(size_t)(q * 512 + d0 + j) * 512 + k]);
    }
    for (int v = tid; v < 512; v += 256) {
        int i = v >> 4, j = v & 15;
        int b = (r0 + i) & 63;
        Cs[i * 16 + j] = c0[b * 512 + d0 + j];
    }
    if (tid < 32) Ls[tid] = lengths[(r0 + tid) & 63];
    __syncthreads();

    for (int t = 0; t < T_; t++) {
        const int cur = t & 1, nxt = cur ^ 1;

        // prefetch gate init from gx (independent of the barrier)
        wmma::fragment<wmma::accumulator, 16, 16, 8, float> cf;
        wmma::load_matrix_sync(cf,
            d_gx + ((size_t)t * R_ + (r0 + wm * 16)) * G_ + wn * 512 + d0,
            G_, wmma::mem_row_major);

        // grid barrier: wait for all CTAs to have finished step t-1
        if (tid == 0) {
            unsigned target = 128u * (unsigned)t;
            while (*(volatile unsigned*)&d_cnt < target) {}
        }
        __syncthreads();

        // gates += H(t) @ Whh_slice^T
#pragma unroll 1
        for (int kc = 0; kc < 8; kc++) {
            for (int v = tid; v < 512; v += 256) {
                int i = v >> 4, c4 = v & 15;
                float4 h4 = __ldcg((const float4*)(d_Hbuf + cur * (R_ * H_) +
                                                   (r0 + i) * H_ + kc * 64 + c4 * 4));
                *(float4*)&Hs[i * 72 + c4 * 4] = h4;
            }
            __syncthreads();
#pragma unroll
            for (int ks = 0; ks < 8; ks++) {
                wmma::fragment<wmma::matrix_a, 16, 16, 8, wmma::precision::tf32, wmma::row_major> af;
                wmma::fragment<wmma::matrix_b, 16, 16, 8, wmma::precision::tf32, wmma::col_major> bf;
                wmma::load_matrix_sync(af, &Hs[wm * 16 * 72 + ks * 8], 72);
                wmma::load_matrix_sync(bf, &Ws[wn * 16 * 520 + kc * 64 + ks * 8], 520);
                wmma::mma_sync(cf, af, bf, cf);
            }
            __syncthreads();
        }

        wmma::store_matrix_sync(&Gs[wm * 16 * 68 + wn * 16], cf, 68, wmma::mem_row_major);
        __syncthreads();

        // elementwise LSTM cell update (CTA owns all four gates of its dims)
        for (int v = tid; v < 512; v += 256) {
            int i = v >> 4, j = v & 15;
            float ig = Gs[i * 68 + j];
            float fg = Gs[i * 68 + 16 + j];
            float gg = Gs[i * 68 + 32 + j];
            float og = Gs[i * 68 + 48 + j];
            float c = Cs[i * 16 + j];
            float si = 1.f / (1.f + expf(-ig));
            float sf = 1.f / (1.f + expf(-fg));
            float so = 1.f / (1.f + expf(-og));
            c = sf * c + si * tanhf(gg);
            float h = so * tanhf(c);
            Cs[i * 16 + j] = c;
            int r = r0 + i;
            d_Hbuf[nxt * (R_ * H_) + r * H_ + d0 + j] = tf32r(h);
            if (t == Ls[i] - 1) {
                int b = r & 63, s = r >> 6;
                d_hfin[b * 1024 + s * 512 + d0 + j] = h;   // exact fp32
            }
        }
        __threadfence();
        __syncthreads();
        if (tid == 0) atomicAdd(&d_cnt, 1u);
    }
}

// ================= K5: readout  out = sigmoid(hfin @ W_o^T + b_o) ==========
__global__ void k_out(const float* __restrict__ Wo, const float* __restrict__ bo,
                      float* __restrict__ out) {
    int b = blockIdx.x;
    int f = threadIdx.x >> 5;
    int lane = threadIdx.x & 31;
    if (f >= 14) return;
    float acc = 0.f;
    for (int k = lane; k < 1024; k += 32)
        acc += d_hfin[b * 1024 + k] * Wo[f * 1024 + k];
    acc = wred(acc);
    if (lane == 0)
        out[b * 14 + f] = 1.f / (1.f + expf(-(acc + bo[f])));
}

// ================= launch ==================================================
extern "C" void kernel_launch(void* const* d_in, const int* in_sizes, int n_in,
                              void* d_out, int out_size) {
    const float* x     = (const float*)d_in[0];
    const int*   len   = (const int*)  d_in[1];
    const float* h0    = (const float*)d_in[2];
    const float* c0    = (const float*)d_in[3];
    const float* Wis0  = (const float*)d_in[4];
    const float* bis0  = (const float*)d_in[5];
    const float* Wis1  = (const float*)d_in[6];
    const float* bis1  = (const float*)d_in[7];
    const float* Wih   = (const float*)d_in[8];
    const float* Whh   = (const float*)d_in[9];
    const float* bih   = (const float*)d_in[10];
    const float* bhh   = (const float*)d_in[11];
    const float* Wo    = (const float*)d_in[12];
    const float* bo    = (const float*)d_in[13];
    float* out = (float*)d_out;

    // no static guard (rules); attribute set is idempotent and capture-legal
    cudaFuncSetAttribute(k_rnn, cudaFuncAttributeMaxDynamicSharedMemorySize,
                         RNN_SMEM_BYTES);

    k_setup<<<256, 256>>>(Wih, Wis0, bis0, Wis1, bis1, bih, bhh);
    k_emb<<<NROW, 128>>>(x);
    k_init<<<R_, 256>>>(h0);
    k_gemm1<<<dim3(G_ / 128, NROW / 128), 256>>>(x, Wih);

    k_rnn<<<R_, 256, RNN_SMEM_BYTES>>>(Whh, c0, len);

    k_out<<<B_, 448>>>(Wo, bo, out);
}

// round 9
// speedup vs baseline: 1.4563x; 1.4563x over previous
#include <cuda_runtime.h>
#include <cuda_bf16.h>
#include <mma.h>
#include <cstdint>

using namespace nvcuda;

// ---------------- problem constants ----------------
#define B_   64
#define T_   128
#define F_   16
#define H_   512
#define G_   2048          // 4*H
#define R_   128           // S*B rows in recurrence
#define NROW 8192          // B*T
#define KE   1024          // t_emb width

// ---------------- static device scratch (no allocation) ----------------
__device__ float d_Emb[(size_t)NROW * KE];          // 32 MB tf32-rounded t_emb
__device__ float d_Wt[(size_t)G_ * KE];             //  8 MB tf32-rounded W_ih[:,512:1536]
__device__ float d_gx[(size_t)T_ * R_ * G_];        // 128 MB per-step gate inputs
__device__ float d_Wc0[G_ * 8];
__device__ float d_Wc1[G_ * 6];
__device__ float d_b0[G_];
__device__ float d_b1[G_];
__device__ float d_Hbuf[2 * R_ * H_];               // double-buffered h (tf32-rounded)
__device__ float d_hfin[B_ * 2 * H_];               // exact h at lengths-1
__device__ unsigned d_cntB[4];                      // per-rowblock barrier counters

__device__ __forceinline__ float tf32r(float x) {
    unsigned u;
    asm("cvt.rna.tf32.f32 %0, %1;" : "=r"(u) : "f"(x));
    return __uint_as_float(u);
}

__device__ __forceinline__ float wred(float v) {
#pragma unroll
    for (int o = 16; o; o >>= 1) v += __shfl_down_sync(0xffffffffu, v, o);
    return v;
}

__device__ __forceinline__ uint32_t s2u(const void* p) {
    uint32_t a;
    asm("{ .reg .u64 t; cvta.to.shared.u64 t, %1; cvt.u32.u64 %0, t; }"
        : "=r"(a) : "l"(p));
    return a;
}
__device__ __forceinline__ void cpa16(uint32_t d, const void* s) {
    asm volatile("cp.async.cg.shared.global [%0], [%1], 16;" :: "r"(d), "l"(s));
}
#define CPCOMMIT() asm volatile("cp.async.commit_group;" ::: "memory")
#define CPWAIT0()  asm volatile("cp.async.wait_group 0;" ::: "memory")

__device__ __forceinline__ float sigf(float x) { return 1.f / (1.f + __expf(-x)); }
__device__ __forceinline__ float tanhfast(float x) {
    float e = __expf(2.f * x);
    return 1.f - 2.f / (e + 1.f);
}

// ================= K0: fold input linears through W_ih[:, :512] ============
__global__ void k_setup(const float* __restrict__ Wih,
                        const float* __restrict__ Wis0, const float* __restrict__ bis0,
                        const float* __restrict__ Wis1, const float* __restrict__ bis1,
                        const float* __restrict__ bih,  const float* __restrict__ bhh) {
    if (blockIdx.x == 0 && threadIdx.x < 4) d_cntB[threadIdx.x] = 0u;
    int gw = (blockIdx.x * blockDim.x + threadIdx.x) >> 5;
    int lane = threadIdx.x & 31;
    if (gw >= G_) return;
    float a0[8], a1[6], s0 = 0.f, s1 = 0.f;
#pragma unroll
    for (int j = 0; j < 8; j++) a0[j] = 0.f;
#pragma unroll
    for (int j = 0; j < 6; j++) a1[j] = 0.f;
    const float* wr = Wih + (size_t)gw * 1536;
    for (int k = lane; k < 512; k += 32) {
        float w = wr[k];
#pragma unroll
        for (int j = 0; j < 8; j++) a0[j] += w * Wis0[k * 8 + j];
#pragma unroll
        for (int j = 0; j < 6; j++) a1[j] += w * Wis1[k * 6 + j];
        s0 += w * bis0[k];
        s1 += w * bis1[k];
    }
#pragma unroll
    for (int j = 0; j < 8; j++) a0[j] = wred(a0[j]);
#pragma unroll
    for (int j = 0; j < 6; j++) a1[j] = wred(a1[j]);
    s0 = wred(s0); s1 = wred(s1);
    if (lane == 0) {
#pragma unroll
        for (int j = 0; j < 8; j++) d_Wc0[gw * 8 + j] = a0[j];
#pragma unroll
        for (int j = 0; j < 6; j++) d_Wc1[gw * 6 + j] = a1[j];
        float bb = bih[gw] + bhh[gw];
        d_b0[gw] = bb + s0;
        d_b1[gw] = bb + s1;
    }
}

// ================= K0b: pre-round W_ih[:,512:1536] into d_Wt ===============
__global__ void k_wr(const float* __restrict__ Wih) {
    size_t g = blockIdx.x;
    const float* src = Wih + g * 1536 + 512;
    float* dst = d_Wt + g * KE;
    for (int k = threadIdx.x; k < KE; k += 256) dst[k] = tf32r(src[k]);
}

// ================= K1: timestep embeddings (MUFU sincos, tf32-rounded) =====
__global__ void k_emb(const float* __restrict__ x) {
    int n = blockIdx.x;
    int j = threadIdx.x;                 // 0..255
    float x0 = x[n * 16 + 0];
    float x1 = x[n * 16 + 1];
    float f = __expf(-0.03597789208f * (float)j);  // ln(10000)/256
    float s0, c0, s1, c1;
    __sincosf(x0 * f, &s0, &c0);
    __sincosf(x1 * f, &s1, &c1);
    float* row = d_Emb + (size_t)n * KE;
    row[j]       = tf32r(c0);
    row[j + 256] = tf32r(s0);
    row[j + 512] = tf32r(c1);
    row[j + 768] = tf32r(s1);
}

// ================= K2: init H(0) for both segments =========================
__global__ void k_init(const float* __restrict__ h0) {
    int r = blockIdx.x;
    int b = r & 63;
    for (int d = threadIdx.x; d < H_; d += blockDim.x)
        d_Hbuf[r * H_ + d] = tf32r(h0[b * H_ + d]);
}

// ================= K3: big GEMM  gx = Emb @ Wt^T (+ e-part, dual parity) ===
// CTA tile 128x128, K=1024 in 32 chunks of 32, cp.async double-buffered.
#define GEMM_SMEM_BYTES ((2 * 4608 * 2 + 8 * 320 + 128 * 14 + 128 * 16) * 4)
__global__ __launch_bounds__(256) void k_gemm1(const float* __restrict__ x) {
    extern __shared__ float sm[];
    float* As = sm;                      // 2 bufs x 128x36
    float* Bs = As + 2 * 4608;
    float* Pt = Bs + 2 * 4608;           // 8 x 320
    float* Xs = Pt + 8 * 320;            // 128 x 14
    float* Wc = Xs + 128 * 14;           // 128 x 16

    const int g0 = blockIdx.x * 128;
    const int m0 = blockIdx.y * 128;
    const int tid = threadIdx.x;
    const int wid = tid >> 5, lane = tid & 31;
    const int wm = wid >> 2, wn = wid & 3;       // warps 2(M) x 4(N)
    const uint32_t uAs = s2u(As), uBs = s2u(Bs);

    for (int v = tid; v < 128 * 14; v += 256) {
        int i = v / 14, j = v - i * 14;
        Xs[v] = x[(m0 + i) * 16 + 2 + j];
    }
    for (int v = tid; v < 2048; v += 256) {
        int c = v >> 4, j = v & 15;
        int gg = g0 + c;
        float val;
        if (j < 8)        val = d_Wc0[gg * 8 + j];
        else if (j < 14)  val = d_Wc1[gg * 6 + (j - 8)];
        else if (j == 14) val = d_b0[gg];
        else              val = d_b1[gg];
        Wc[v] = val;
    }

    wmma::fragment<wmma::accumulator, 16, 16, 8, float> acc[4][2];
#pragma unroll
    for (int i = 0; i < 4; i++)
#pragma unroll
        for (int j = 0; j < 2; j++) wmma::fill_fragment(acc[i][j], 0.0f);

    // stage chunk 0
    {
        const float* eb = d_Emb + (size_t)m0 * KE;
        const float* wb = d_Wt + (size_t)g0 * KE;
#pragma unroll
        for (int it = 0; it < 4; it++) {
            int v = tid + 256 * it;
            int i = v >> 3, c4 = v & 7;
            cpa16(uAs + (uint32_t)(i * 36 + c4 * 4) * 4, eb + (size_t)i * KE + c4 * 4);
            cpa16(uBs + (uint32_t)(i * 36 + c4 * 4) * 4, wb + (size_t)i * KE + c4 * 4);
        }
        CPCOMMIT();
    }

    for (int kc = 0; kc < 32; kc++) {
        CPWAIT0();
        __syncthreads();
        if (kc < 31) {
            int nb = (kc + 1) & 1;
            const float* eb = d_Emb + (size_t)m0 * KE + (kc + 1) * 32;
            const float* wb = d_Wt + (size_t)g0 * KE + (kc + 1) * 32;
#pragma unroll
            for (int it = 0; it < 4; it++) {
                int v = tid + 256 * it;
                int i = v >> 3, c4 = v & 7;
                cpa16(uAs + (uint32_t)(nb * 4608 + i * 36 + c4 * 4) * 4,
                      eb + (size_t)i * KE + c4 * 4);
                cpa16(uBs + (uint32_t)(nb * 4608 + i * 36 + c4 * 4) * 4,
                      wb + (size_t)i * KE + c4 * 4);
            }
            CPCOMMIT();
        }
        const float* Ab = As + (kc & 1) * 4608;
        const float* Bb = Bs + (kc & 1) * 4608;
#pragma unroll
        for (int ks = 0; ks < 4; ks++) {
            wmma::fragment<wmma::matrix_b, 16, 16, 8, wmma::precision::tf32, wmma::col_major> bf[2];
#pragma unroll
            for (int nn = 0; nn < 2; nn++)
                wmma::load_matrix_sync(bf[nn], Bb + (wn * 32 + nn * 16) * 36 + ks * 8, 36);
#pragma unroll
            for (int tm = 0; tm < 4; tm++) {
                wmma::fragment<wmma::matrix_a, 16, 16, 8, wmma::precision::tf32, wmma::row_major> af;
                wmma::load_matrix_sync(af, Ab + (wm * 64 + tm * 16) * 36 + ks * 8, 36);
#pragma unroll
                for (int nn = 0; nn < 2; nn++)
                    wmma::mma_sync(acc[tm][nn], af, bf[nn], acc[tm][nn]);
            }
        }
    }

    // epilogue: write both parities with folded e-parts + biases
#pragma unroll
    for (int nn = 0; nn < 2; nn++) {
        int cl = wn * 32 + nn * 16 + (lane & 15);
        float wcj[14];
#pragma unroll
        for (int j = 0; j < 14; j++) wcj[j] = Wc[cl * 16 + j];
        float bb0 = Wc[cl * 16 + 14], bb1 = Wc[cl * 16 + 15];
        int g = g0 + cl;
#pragma unroll
        for (int tm = 0; tm < 4; tm++) {
            wmma::store_matrix_sync(&Pt[wid * 320], acc[tm][nn], 20, wmma::mem_row_major);
            __syncwarp();
#pragma unroll
            for (int i2 = 0; i2 < 8; i2++) {
                int pr = (lane >> 4) + 2 * i2;
                int ml = wm * 64 + tm * 16 + pr;
                float dd = Pt[wid * 320 + pr * 20 + (lane & 15)];
                float e0 = 0.f, e1 = 0.f;
#pragma unroll
                for (int j = 0; j < 8; j++) e0 += Xs[ml * 14 + j] * wcj[j];
#pragma unroll
                for (int j = 0; j < 6; j++) e1 += Xs[ml * 14 + 8 + j] * wcj[8 + j];
                int n = m0 + ml;
                int b = n >> 7, rem = n & 127;
                int s = rem >> 6, u = rem & 63;
                int r = s * 64 + b;
                size_t base = ((size_t)(2 * u) * R_ + r) * G_ + g;
                d_gx[base] = dd + e0 + bb0;
                d_gx[base + (size_t)R_ * G_] = dd + e1 + bb1;
            }
            __syncwarp();
        }
    }
}

// ================= K4: persistent LSTM recurrence ==========================
// 128 CTAs: rb=cid>>5 (32 rows), dg=cid&31 (16 dims -> 4x16 gate cols).
// Per-rowblock barrier; cp.async double-buffered H staging (4 chunks of 128).
#define RNN_SMEM_BYTES ((64 * 520 + 2 * 32 * 136 + 32 * 68 + 32 * 16) * 4 + 32 * 4)
__global__ __launch_bounds__(256) void k_rnn(const float* __restrict__ Whh,
                                             const float* __restrict__ c0,
                                             const int* __restrict__ lengths) {
    extern __shared__ float sm[];
    float* Ws = sm;                      // 64 x 520
    float* Hs = Ws + 64 * 520;           // 2 bufs x 32 x 136
    float* Gs = Hs + 2 * 4352;           // 32 x 68
    float* Cs = Gs + 32 * 68;            // 32 x 16
    int*   Ls = (int*)(Cs + 32 * 16);    // 32

    const int cid = blockIdx.x;
    const int rb = cid >> 5, dg = cid & 31;
    const int r0 = rb * 32, d0 = dg * 16;
    const int tid = threadIdx.x;
    const int wid = tid >> 5;
    const int wm = wid >> 2, wn = wid & 3;   // warps 2(M rows) x 4(gate q)
    const uint32_t uHs = s2u(Hs);

    for (int idx = tid; idx < 64 * 512; idx += 256) {
        int row = idx >> 9, k = idx & 511;
        int q = row >> 4, j = row & 15;
        Ws[row * 520 + k] = tf32r(Whh[(size_t)(q * 512 + d0 + j) * 512 + k]);
    }
    for (int v = tid; v < 512; v += 256) {
        int i = v >> 4, j = v & 15;
        int b = (r0 + i) & 63;
        Cs[i * 16 + j] = c0[b * 512 + d0 + j];
    }
    if (tid < 32) Ls[tid] = lengths[(r0 + tid) & 63];
    __syncthreads();

    for (int t = 0; t < T_; t++) {
        const int cur = t & 1, nxt = cur ^ 1;

        // prefetch gate init from gx (independent of the barrier)
        wmma::fragment<wmma::accumulator, 16, 16, 8, float> cf;
        wmma::load_matrix_sync(cf,
            d_gx + ((size_t)t * R_ + (r0 + wm * 16)) * G_ + wn * 512 + d0,
            G_, wmma::mem_row_major);

        // rowblock barrier: wait until all 32 CTAs finished step t-1
        if (tid == 0) {
            unsigned target = 32u * (unsigned)t;
            while (*(volatile unsigned*)&d_cntB[rb] < target) {}
        }
        __syncthreads();

        const float* hb = d_Hbuf + (size_t)cur * (R_ * H_) + (size_t)r0 * H_;
        // stage chunk 0
#pragma unroll
        for (int it = 0; it < 4; it++) {
            int v = tid + 256 * it;
            int i = v >> 5, c4 = v & 31;
            cpa16(uHs + (uint32_t)(i * 136 + c4 * 4) * 4, hb + (size_t)i * H_ + c4 * 4);
        }
        CPCOMMIT();

#pragma unroll
        for (int kc = 0; kc < 4; kc++) {
            CPWAIT0();
            __syncthreads();
            if (kc < 3) {
                int nb = (kc + 1) & 1;
                const float* hc = hb + (kc + 1) * 128;
#pragma unroll
                for (int it = 0; it < 4; it++) {
                    int v = tid + 256 * it;
                    int i = v >> 5, c4 = v & 31;
                    cpa16(uHs + (uint32_t)(nb * 4352 + i * 136 + c4 * 4) * 4,
                          hc + (size_t)i * H_ + c4 * 4);
                }
                CPCOMMIT();
            }
            const float* Hb = Hs + (kc & 1) * 4352;
#pragma unroll
            for (int ks = 0; ks < 16; ks++) {
                wmma::fragment<wmma::matrix_a, 16, 16, 8, wmma::precision::tf32, wmma::row_major> af;
                wmma::fragment<wmma::matrix_b, 16, 16, 8, wmma::precision::tf32, wmma::col_major> bf;
                wmma::load_matrix_sync(af, Hb + (wm * 16) * 136 + ks * 8, 136);
                wmma::load_matrix_sync(bf, Ws + (wn * 16) * 520 + kc * 128 + ks * 8, 520);
                wmma::mma_sync(cf, af, bf, cf);
            }
        }

        wmma::store_matrix_sync(&Gs[wm * 16 * 68 + wn * 16], cf, 68, wmma::mem_row_major);
        __syncthreads();

        // elementwise LSTM cell update
        for (int v = tid; v < 512; v += 256) {
            int i = v >> 4, j = v & 15;
            float ig = Gs[i * 68 + j];
            float fg = Gs[i * 68 + 16 + j];
            float gg = Gs[i * 68 + 32 + j];
            float og = Gs[i * 68 + 48 + j];
            float c = Cs[i * 16 + j];
            c = sigf(fg) * c + sigf(ig) * tanhfast(gg);
            float h = sigf(og) * tanhfast(c);
            Cs[i * 16 + j] = c;
            int r = r0 + i;
            d_Hbuf[nxt * (R_ * H_) + r * H_ + d0 + j] = tf32r(h);
            if (t == Ls[i] - 1) {
                int b = r & 63, s = r >> 6;
                d_hfin[b * 1024 + s * 512 + d0 + j] = h;   // exact fp32
            }
        }
        __threadfence();
        __syncthreads();
        if (tid == 0) atomicAdd(&d_cntB[rb], 1u);
    }
}

// ================= K5: readout  out = sigmoid(hfin @ W_o^T + b_o) ==========
__global__ void k_out(const float* __restrict__ Wo, const float* __restrict__ bo,
                      float* __restrict__ out) {
    int b = blockIdx.x;
    int f = threadIdx.x >> 5;
    int lane = threadIdx.x & 31;
    if (f >= 14) return;
    float acc = 0.f;
    for (int k = lane; k < 1024; k += 32)
        acc += d_hfin[b * 1024 + k] * Wo[f * 1024 + k];
    acc = wred(acc);
    if (lane == 0)
        out[b * 14 + f] = 1.f / (1.f + __expf(-(acc + bo[f])));
}

// ================= launch ==================================================
extern "C" void kernel_launch(void* const* d_in, const int* in_sizes, int n_in,
                              void* d_out, int out_size) {
    const float* x     = (const float*)d_in[0];
    const int*   len   = (const int*)  d_in[1];
    const float* h0    = (const float*)d_in[2];
    const float* c0    = (const float*)d_in[3];
    const float* Wis0  = (const float*)d_in[4];
    const float* bis0  = (const float*)d_in[5];
    const float* Wis1  = (const float*)d_in[6];
    const float* bis1  = (const float*)d_in[7];
    const float* Wih   = (const float*)d_in[8];
    const float* Whh   = (const float*)d_in[9];
    const float* bih   = (const float*)d_in[10];
    const float* bhh   = (const float*)d_in[11];
    const float* Wo    = (const float*)d_in[12];
    const float* bo    = (const float*)d_in[13];
    float* out = (float*)d_out;

    cudaFuncSetAttribute(k_gemm1, cudaFuncAttributeMaxDynamicSharedMemorySize,
                         GEMM_SMEM_BYTES);
    cudaFuncSetAttribute(k_rnn, cudaFuncAttributeMaxDynamicSharedMemorySize,
                         RNN_SMEM_BYTES);

    k_setup<<<256, 256>>>(Wih, Wis0, bis0, Wis1, bis1, bih, bhh);
    k_wr<<<G_, 256>>>(Wih);
    k_emb<<<NROW, 256>>>(x);
    k_init<<<R_, 256>>>(h0);
    k_gemm1<<<dim3(G_ / 128, NROW / 128), 256, GEMM_SMEM_BYTES>>>(x);
    k_rnn<<<R_, 256, RNN_SMEM_BYTES>>>(Whh, c0, len);
    k_out<<<B_, 448>>>(Wo, bo, out);
}

// round 10
// speedup vs baseline: 3.3303x; 2.2868x over previous
#include <cuda_runtime.h>
#include <cuda_bf16.h>
#include <mma.h>
#include <cstdint>

using namespace nvcuda;

// ---------------- problem constants ----------------
#define B_   64
#define T_   128
#define F_   16
#define H_   512
#define G_   2048          // 4*H
#define R_   128           // S*B rows in recurrence
#define NROW 8192          // B*T
#define KE   1024          // t_emb width

typedef __nv_bfloat16 bf16;

// ---------------- static device scratch (no allocation) ----------------
__device__ bf16  d_Emb[(size_t)NROW * KE];          // 16 MB bf16 t_emb
__device__ bf16  d_Wt[(size_t)G_ * KE];             //  4 MB bf16 W_ih[:,512:1536]
__device__ float d_gx[(size_t)T_ * R_ * G_];        // 128 MB per-step gate inputs
__device__ float d_Wc0[G_ * 8];
__device__ float d_Wc1[G_ * 6];
__device__ float d_b0[G_];
__device__ float d_b1[G_];
__device__ bf16  d_Hbuf[2 * R_ * H_];               // double-buffered h (bf16)
__device__ float d_hfin[B_ * 2 * H_];               // exact h at lengths-1
__device__ unsigned d_cntB[4];                      // per-rowblock barrier counters

__device__ __forceinline__ float wred(float v) {
#pragma unroll
    for (int o = 16; o; o >>= 1) v += __shfl_down_sync(0xffffffffu, v, o);
    return v;
}

__device__ __forceinline__ uint32_t s2u(const void* p) {
    uint32_t a;
    asm("{ .reg .u64 t; cvta.to.shared.u64 t, %1; cvt.u32.u64 %0, t; }"
        : "=r"(a) : "l"(p));
    return a;
}
__device__ __forceinline__ void cpa16(uint32_t d, const void* s) {
    asm volatile("cp.async.cg.shared.global [%0], [%1], 16;" :: "r"(d), "l"(s));
}
#define CPCOMMIT() asm volatile("cp.async.commit_group;" ::: "memory")
#define CPWAIT0()  asm volatile("cp.async.wait_group 0;" ::: "memory")

__device__ __forceinline__ void bar_arrive(unsigned* p) {
    asm volatile("red.release.gpu.add.u32 [%0], 1;" :: "l"(p) : "memory");
}
__device__ __forceinline__ unsigned bar_poll(const unsigned* p) {
    unsigned v;
    asm volatile("ld.acquire.gpu.u32 %0, [%1];" : "=r"(v) : "l"(p) : "memory");
    return v;
}

__device__ __forceinline__ float sigf(float x) { return 1.f / (1.f + __expf(-x)); }
__device__ __forceinline__ float tanhfast(float x) {
    float e = __expf(2.f * x);
    return 1.f - 2.f / (e + 1.f);
}

// ================= K0: fold input linears through W_ih[:, :512] ============
__global__ void k_setup(const float* __restrict__ Wih,
                        const float* __restrict__ Wis0, const float* __restrict__ bis0,
                        const float* __restrict__ Wis1, const float* __restrict__ bis1,
                        const float* __restrict__ bih,  const float* __restrict__ bhh) {
    if (blockIdx.x == 0 && threadIdx.x < 4) d_cntB[threadIdx.x] = 0u;
    int gw = (blockIdx.x * blockDim.x + threadIdx.x) >> 5;
    int lane = threadIdx.x & 31;
    if (gw >= G_) return;
    float a0[8], a1[6], s0 = 0.f, s1 = 0.f;
#pragma unroll
    for (int j = 0; j < 8; j++) a0[j] = 0.f;
#pragma unroll
    for (int j = 0; j < 6; j++) a1[j] = 0.f;
    const float* wr = Wih + (size_t)gw * 1536;
    for (int k = lane; k < 512; k += 32) {
        float w = wr[k];
#pragma unroll
        for (int j = 0; j < 8; j++) a0[j] += w * Wis0[k * 8 + j];
#pragma unroll
        for (int j = 0; j < 6; j++) a1[j] += w * Wis1[k * 6 + j];
        s0 += w * bis0[k];
        s1 += w * bis1[k];
    }
#pragma unroll
    for (int j = 0; j < 8; j++) a0[j] = wred(a0[j]);
#pragma unroll
    for (int j = 0; j < 6; j++) a1[j] = wred(a1[j]);
    s0 = wred(s0); s1 = wred(s1);
    if (lane == 0) {
#pragma unroll
        for (int j = 0; j < 8; j++) d_Wc0[gw * 8 + j] = a0[j];
#pragma unroll
        for (int j = 0; j < 6; j++) d_Wc1[gw * 6 + j] = a1[j];
        float bb = bih[gw] + bhh[gw];
        d_b0[gw] = bb + s0;
        d_b1[gw] = bb + s1;
    }
}

// ================= K0b: convert W_ih[:,512:1536] to bf16 ===================
__global__ void k_wr(const float* __restrict__ Wih) {
    size_t g = blockIdx.x;
    const float* src = Wih + g * 1536 + 512;
    bf16* dst = d_Wt + g * KE;
    for (int k = threadIdx.x; k < KE; k += 256)
        dst[k] = __float2bfloat16_rn(src[k]);
}

// ================= K1: timestep embeddings (MUFU sincos, bf16) =============
__global__ void k_emb(const float* __restrict__ x) {
    int n = blockIdx.x;
    int j = threadIdx.x;                 // 0..255
    float x0 = x[n * 16 + 0];
    float x1 = x[n * 16 + 1];
    float f = __expf(-0.03597789208f * (float)j);  // ln(10000)/256
    float s0, c0, s1, c1;
    __sincosf(x0 * f, &s0, &c0);
    __sincosf(x1 * f, &s1, &c1);
    bf16* row = d_Emb + (size_t)n * KE;
    row[j]       = __float2bfloat16_rn(c0);
    row[j + 256] = __float2bfloat16_rn(s0);
    row[j + 512] = __float2bfloat16_rn(c1);
    row[j + 768] = __float2bfloat16_rn(s1);
}

// ================= K2: init H(0) for both segments =========================
__global__ void k_init(const float* __restrict__ h0) {
    int r = blockIdx.x;
    int b = r & 63;
    for (int d = threadIdx.x; d < H_; d += blockDim.x)
        d_Hbuf[r * H_ + d] = __float2bfloat16_rn(h0[b * H_ + d]);
}

// ================= K3: big GEMM  gx = Emb @ Wt^T (+ e-part, dual parity) ===
// CTA tile 128x128, K=1024 in 32 chunks of 32 (2x k16), cp.async double-buf.
#define GA_STR 40
#define GA_BUF (128 * GA_STR)            // bf16 elems per buffer
#define GEMM_SMEM_BYTES (2 * GA_BUF * 2 * 2 + (8 * 320 + 128 * 14 + 128 * 16) * 4)
__global__ __launch_bounds__(256, 2) void k_gemm1(const float* __restrict__ x) {
    extern __shared__ char smraw[];
    bf16*  As = (bf16*)smraw;                     // 2 bufs x 128x40
    bf16*  Bs = As + 2 * GA_BUF;                  // 2 bufs x 128x40
    float* Pt = (float*)(Bs + 2 * GA_BUF);        // 8 x 320
    float* Xs = Pt + 8 * 320;                     // 128 x 14
    float* Wc = Xs + 128 * 14;                    // 128 x 16

    const int g0 = blockIdx.x * 128;
    const int m0 = blockIdx.y * 128;
    const int tid = threadIdx.x;
    const int wid = tid >> 5, lane = tid & 31;
    const int wm = wid >> 2, wn = wid & 3;        // warps 2(M) x 4(N)
    const uint32_t uAs = s2u(As), uBs = s2u(Bs);

    for (int v = tid; v < 128 * 14; v += 256) {
        int i = v / 14, j = v - i * 14;
        Xs[v] = x[(m0 + i) * 16 + 2 + j];
    }
    for (int v = tid; v < 2048; v += 256) {
        int c = v >> 4, j = v & 15;
        int gg = g0 + c;
        float val;
        if (j < 8)        val = d_Wc0[gg * 8 + j];
        else if (j < 14)  val = d_Wc1[gg * 6 + (j - 8)];
        else if (j == 14) val = d_b0[gg];
        else              val = d_b1[gg];
        Wc[v] = val;
    }

    wmma::fragment<wmma::accumulator, 16, 16, 16, float> acc[4][2];
#pragma unroll
    for (int i = 0; i < 4; i++)
#pragma unroll
        for (int j = 0; j < 2; j++) wmma::fill_fragment(acc[i][j], 0.0f);

    // stage chunk 0: 128 rows x 32 bf16 cols = 512 x 16B per matrix
    {
        const bf16* eb = d_Emb + (size_t)m0 * KE;
        const bf16* wb = d_Wt + (size_t)g0 * KE;
#pragma unroll
        for (int it = 0; it < 2; it++) {
            int v = tid + 256 * it;
            int i = v >> 2, c4 = v & 3;
            cpa16(uAs + (uint32_t)(i * GA_STR + c4 * 8) * 2, eb + (size_t)i * KE + c4 * 8);
            cpa16(uBs + (uint32_t)(i * GA_STR + c4 * 8) * 2, wb + (size_t)i * KE + c4 * 8);
        }
        CPCOMMIT();
    }

    for (int kc = 0; kc < 32; kc++) {
        CPWAIT0();
        __syncthreads();
        if (kc < 31) {
            int nb = (kc + 1) & 1;
            const bf16* eb = d_Emb + (size_t)m0 * KE + (kc + 1) * 32;
            const bf16* wb = d_Wt + (size_t)g0 * KE + (kc + 1) * 32;
#pragma unroll
            for (int it = 0; it < 2; it++) {
                int v = tid + 256 * it;
                int i = v >> 2, c4 = v & 3;
                cpa16(uAs + (uint32_t)(nb * GA_BUF + i * GA_STR + c4 * 8) * 2,
                      eb + (size_t)i * KE + c4 * 8);
                cpa16(uBs + (uint32_t)(nb * GA_BUF + i * GA_STR + c4 * 8) * 2,
                      wb + (size_t)i * KE + c4 * 8);
            }
            CPCOMMIT();
        }
        const bf16* Ab = As + (kc & 1) * GA_BUF;
        const bf16* Bb = Bs + (kc & 1) * GA_BUF;
#pragma unroll
        for (int ks = 0; ks < 2; ks++) {
            wmma::fragment<wmma::matrix_b, 16, 16, 16, bf16, wmma::col_major> bf[2];
#pragma unroll
            for (int nn = 0; nn < 2; nn++)
                wmma::load_matrix_sync(bf[nn], Bb + (wn * 32 + nn * 16) * GA_STR + ks * 16, GA_STR);
#pragma unroll
            for (int tm = 0; tm < 4; tm++) {
                wmma::fragment<wmma::matrix_a, 16, 16, 16, bf16, wmma::row_major> af;
                wmma::load_matrix_sync(af, Ab + (wm * 64 + tm * 16) * GA_STR + ks * 16, GA_STR);
#pragma unroll
                for (int nn = 0; nn < 2; nn++)
                    wmma::mma_sync(acc[tm][nn], af, bf[nn], acc[tm][nn]);
            }
        }
    }

    // epilogue: write both parities with folded e-parts + biases (fp32)
#pragma unroll
    for (int nn = 0; nn < 2; nn++) {
        int cl = wn * 32 + nn * 16 + (lane & 15);
        float wcj[14];
#pragma unroll
        for (int j = 0; j < 14; j++) wcj[j] = Wc[cl * 16 + j];
        float bb0 = Wc[cl * 16 + 14], bb1 = Wc[cl * 16 + 15];
        int g = g0 + cl;
#pragma unroll
        for (int tm = 0; tm < 4; tm++) {
            wmma::store_matrix_sync(&Pt[wid * 320], acc[tm][nn], 20, wmma::mem_row_major);
            __syncwarp();
#pragma unroll
            for (int i2 = 0; i2 < 8; i2++) {
                int pr = (lane >> 4) + 2 * i2;
                int ml = wm * 64 + tm * 16 + pr;
                float dd = Pt[wid * 320 + pr * 20 + (lane & 15)];
                float e0 = 0.f, e1 = 0.f;
#pragma unroll
                for (int j = 0; j < 8; j++) e0 += Xs[ml * 14 + j] * wcj[j];
#pragma unroll
                for (int j = 0; j < 6; j++) e1 += Xs[ml * 14 + 8 + j] * wcj[8 + j];
                int n = m0 + ml;
                int b = n >> 7, rem = n & 127;
                int s = rem >> 6, u = rem & 63;
                int r = s * 64 + b;
                size_t base = ((size_t)(2 * u) * R_ + r) * G_ + g;
                d_gx[base] = dd + e0 + bb0;
                d_gx[base + (size_t)R_ * G_] = dd + e1 + bb1;
            }
            __syncwarp();
        }
    }
}

// ================= K4: persistent LSTM recurrence (bf16 operands) ==========
// 128 CTAs: rb=cid>>5 (32 rows), dg=cid&31 (16 dims -> 4x16 gate cols)
#define WS_STR 520
#define HS_STR 136
#define HS_BUF (32 * HS_STR)
#define RNN_SMEM_BYTES ((64 * WS_STR + 2 * HS_BUF) * 2 + (32 * 68 + 32 * 16) * 4 + 32 * 4)
__global__ __launch_bounds__(256) void k_rnn(const float* __restrict__ Whh,
                                             const float* __restrict__ c0,
                                             const int* __restrict__ lengths) {
    extern __shared__ char smraw[];
    bf16*  Ws = (bf16*)smraw;                    // 64 x 520
    bf16*  Hs = Ws + 64 * WS_STR;                // 2 bufs x 32 x 136
    float* Gs = (float*)(Hs + 2 * HS_BUF);       // 32 x 68
    float* Cs = Gs + 32 * 68;                    // 32 x 16
    int*   Ls = (int*)(Cs + 32 * 16);            // 32

    const int cid = blockIdx.x;
    const int rb = cid >> 5, dg = cid & 31;
    const int r0 = rb * 32, d0 = dg * 16;
    const int tid = threadIdx.x;
    const int wid = tid >> 5;
    const int wm = wid >> 2, wn = wid & 3;       // warps 2(M rows) x 4(gate q)
    const uint32_t uHs = s2u(Hs);

    for (int idx = tid; idx < 64 * 512; idx += 256) {
        int row = idx >> 9, k = idx & 511;
        int q = row >> 4, j = row & 15;
        Ws[row * WS_STR + k] = __float2bfloat16_rn(Whh[(size_t)(q * 512 + d0 + j) * 512 + k]);
    }
    for (int v = tid; v < 512; v += 256) {
        int i = v >> 4, j = v & 15;
        int b = (r0 + i) & 63;
        Cs[i * 16 + j] = c0[b * 512 + d0 + j];
    }
    if (tid < 32) Ls[tid] = lengths[(r0 + tid) & 63];
    __syncthreads();

    for (int t = 0; t < T_; t++) {
        const int cur = t & 1, nxt = cur ^ 1;

        // gate init from gx (barrier-independent prefetch)
        wmma::fragment<wmma::accumulator, 16, 16, 16, float> cf0, cf1;
        wmma::load_matrix_sync(cf0,
            d_gx + ((size_t)t * R_ + (r0 + wm * 16)) * G_ + wn * 512 + d0,
            G_, wmma::mem_row_major);
        wmma::fill_fragment(cf1, 0.0f);

        // rowblock barrier: wait until all 32 CTAs finished step t-1
        if (tid == 0) {
            unsigned target = 32u * (unsigned)t;
            while (bar_poll(&d_cntB[rb]) < target) {}
        }
        __syncthreads();

        const bf16* hb = d_Hbuf + (size_t)cur * (R_ * H_) + (size_t)r0 * H_;
        // stage chunk 0: 32 rows x 128 bf16 = 512 x 16B
#pragma unroll
        for (int it = 0; it < 2; it++) {
            int v = tid + 256 * it;
            int i = v >> 4, c = v & 15;
            cpa16(uHs + (uint32_t)(i * HS_STR + c * 8) * 2, hb + (size_t)i * H_ + c * 8);
        }
        CPCOMMIT();

#pragma unroll
        for (int kc = 0; kc < 4; kc++) {
            CPWAIT0();
            __syncthreads();
            if (kc < 3) {
                int nb = (kc + 1) & 1;
                const bf16* hc = hb + (kc + 1) * 128;
#pragma unroll
                for (int it = 0; it < 2; it++) {
                    int v = tid + 256 * it;
                    int i = v >> 4, c = v & 15;
                    cpa16(uHs + (uint32_t)(nb * HS_BUF + i * HS_STR + c * 8) * 2,
                          hc + (size_t)i * H_ + c * 8);
                }
                CPCOMMIT();
            }
            const bf16* Hb = Hs + (kc & 1) * HS_BUF;
#pragma unroll
            for (int ks = 0; ks < 8; ks++) {
                wmma::fragment<wmma::matrix_a, 16, 16, 16, bf16, wmma::row_major> af;
                wmma::fragment<wmma::matrix_b, 16, 16, 16, bf16, wmma::col_major> bfr;
                wmma::load_matrix_sync(af, Hb + (wm * 16) * HS_STR + ks * 16, HS_STR);
                wmma::load_matrix_sync(bfr, Ws + (wn * 16) * WS_STR + kc * 128 + ks * 16, WS_STR);
                if (ks & 1) wmma::mma_sync(cf1, af, bfr, cf1);
                else        wmma::mma_sync(cf0, af, bfr, cf0);
            }
        }
#pragma unroll
        for (int e = 0; e < cf0.num_elements; e++) cf0.x[e] += cf1.x[e];

        wmma::store_matrix_sync(&Gs[wm * 16 * 68 + wn * 16], cf0, 68, wmma::mem_row_major);
        __syncthreads();

        // elementwise LSTM cell update
        for (int v = tid; v < 512; v += 256) {
            int i = v >> 4, j = v & 15;
            float ig = Gs[i * 68 + j];
            float fg = Gs[i * 68 + 16 + j];
            float gg = Gs[i * 68 + 32 + j];
            float og = Gs[i * 68 + 48 + j];
            float c = Cs[i * 16 + j];
            c = sigf(fg) * c + sigf(ig) * tanhfast(gg);
            float h = sigf(og) * tanhfast(c);
            Cs[i * 16 + j] = c;
            int r = r0 + i;
            d_Hbuf[nxt * (R_ * H_) + r * H_ + d0 + j] = __float2bfloat16_rn(h);
            if (t == Ls[i] - 1) {
                int b = r & 63, s = r >> 6;
                d_hfin[b * 1024 + s * 512 + d0 + j] = h;   // exact fp32
            }
        }
        __syncthreads();
        if (tid == 0) bar_arrive(&d_cntB[rb]);   // release: orders prior stores
    }
}

// ================= K5: readout  out = sigmoid(hfin @ W_o^T + b_o) ==========
__global__ void k_out(const float* __restrict__ Wo, const float* __restrict__ bo,
                      float* __restrict__ out) {
    int b = blockIdx.x;
    int f = threadIdx.x >> 5;
    int lane = threadIdx.x & 31;
    if (f >= 14) return;
    float acc = 0.f;
    for (int k = lane; k < 1024; k += 32)
        acc += d_hfin[b * 1024 + k] * Wo[f * 1024 + k];
    acc = wred(acc);
    if (lane == 0)
        out[b * 14 + f] = 1.f / (1.f + __expf(-(acc + bo[f])));
}

// ================= launch ==================================================
extern "C" void kernel_launch(void* const* d_in, const int* in_sizes, int n_in,
                              void* d_out, int out_size) {
    const float* x     = (const float*)d_in[0];
    const int*   len   = (const int*)  d_in[1];
    const float* h0    = (const float*)d_in[2];
    const float* c0    = (const float*)d_in[3];
    const float* Wis0  = (const float*)d_in[4];
    const float* bis0  = (const float*)d_in[5];
    const float* Wis1  = (const float*)d_in[6];
    const float* bis1  = (const float*)d_in[7];
    const float* Wih   = (const float*)d_in[8];
    const float* Whh   = (const float*)d_in[9];
    const float* bih   = (const float*)d_in[10];
    const float* bhh   = (const float*)d_in[11];
    const float* Wo    = (const float*)d_in[12];
    const float* bo    = (const float*)d_in[13];
    float* out = (float*)d_out;

    cudaFuncSetAttribute(k_gemm1, cudaFuncAttributeMaxDynamicSharedMemorySize,
                         GEMM_SMEM_BYTES);
    cudaFuncSetAttribute(k_rnn, cudaFuncAttributeMaxDynamicSharedMemorySize,
                         RNN_SMEM_BYTES);

    k_setup<<<256, 256>>>(Wih, Wis0, bis0, Wis1, bis1, bih, bhh);
    k_wr<<<G_, 256>>>(Wih);
    k_emb<<<NROW, 256>>>(x);
    k_init<<<R_, 256>>>(h0);
    k_gemm1<<<dim3(G_ / 128, NROW / 128), 256, GEMM_SMEM_BYTES>>>(x);
    k_rnn<<<R_, 256, RNN_SMEM_BYTES>>>(Whh, c0, len);
    k_out<<<B_, 448>>>(Wo, bo, out);
}